// round 1
// baseline (speedup 1.0000x reference)
#include <cuda_runtime.h>
#include <stdint.h>

#define NW      12
#define DIM     4096
#define THREADS 256

// ---------------------------------------------------------------------------
// Host-side GF(2) machinery for the CNOT chain relabeling.
// Wire-space transform rows: y = T x, trow[w] = mask over x-wires.
// Chain: CNOT(w,w+1) for w=0..10, then CNOT(11,0).  CNOT(c,t): row_t ^= row_c.
// Wire w <-> bit (11-w) of the flattened state index.
// ---------------------------------------------------------------------------

struct CircuitMasks {
    int Ma[6], Mb[6];   // pair XOR masks (columns of M^-1), bit space
    int Ra[6], Rb[6];   // branch parity masks (rows of M), bit space
    int p1[6], p2[6];   // zero-insertion positions for coset enumeration (p1<p2)
    int row2[12];       // rows of M^2, bit space (measurement signs)
};

static inline int wire2bits(unsigned wiremask) {
    int m = 0;
    for (int v = 0; v < NW; v++)
        if ((wiremask >> v) & 1) m |= 1 << (11 - v);
    return m;
}

static void compute_masks(CircuitMasks* cm) {
    // rows of M (one chain) and M^2 (two chains), wire space
    unsigned M[NW], M2[NW];
    for (int w = 0; w < NW; w++) M[w] = 1u << w;
    for (int rep = 0; rep < 2; rep++) {
        for (int w = 0; w < NW - 1; w++) M[w + 1] ^= M[w];
        M[0] ^= M[NW - 1];
        if (rep == 0) for (int w = 0; w < NW; w++) M2[w] = M[w];
    }
    // note: after loop, M holds M^2 rows and M2 holds M rows. Fix names:
    unsigned Mrows[NW], M2rows[NW];
    for (int w = 0; w < NW; w++) { Mrows[w] = M2[w]; M2rows[w] = M[w]; }

    // invert Mrows via Gauss-Jordan (wire space)
    unsigned A[NW], Inv[NW];
    for (int i = 0; i < NW; i++) { A[i] = Mrows[i]; Inv[i] = 1u << i; }
    for (int col = 0; col < NW; col++) {
        int piv = -1;
        for (int r = col; r < NW; r++)
            if ((A[r] >> col) & 1) { piv = r; break; }
        unsigned ta = A[col]; A[col] = A[piv]; A[piv] = ta;
        unsigned ti = Inv[col]; Inv[col] = Inv[piv]; Inv[piv] = ti;
        for (int r = 0; r < NW; r++)
            if (r != col && ((A[r] >> col) & 1)) { A[r] ^= A[col]; Inv[r] ^= Inv[col]; }
    }
    // column w of M^-1 (wire space): bit v set iff Inv[v] has bit w
    unsigned colw[NW];
    for (int w = 0; w < NW; w++) {
        unsigned c = 0;
        for (int v = 0; v < NW; v++)
            if ((Inv[v] >> w) & 1) c |= 1u << v;
        colw[w] = c;
    }

    for (int w = 0; w < NW; w++) cm->row2[w] = wire2bits(M2rows[w]);

    for (int pass = 0; pass < 6; pass++) {
        int wa = 2 * pass, wb = 2 * pass + 1;
        int Ma = wire2bits(colw[wa]);
        int Mb = wire2bits(colw[wb]);
        cm->Ma[pass] = Ma;
        cm->Mb[pass] = Mb;
        cm->Ra[pass] = wire2bits(Mrows[wa]);
        cm->Rb[pass] = wire2bits(Mrows[wb]);
        // pivot bits for coset representative enumeration
        int ja = __builtin_ctz((unsigned)Ma);
        int t = Mb;
        if ((t >> ja) & 1) t ^= Ma;
        int jb = __builtin_ctz((unsigned)t);
        cm->p1[pass] = ja < jb ? ja : jb;
        cm->p2[pass] = ja < jb ? jb : ja;
    }
}

// ---------------------------------------------------------------------------
// Device
// ---------------------------------------------------------------------------

__device__ float g_weight[DIM];

__global__ void weight_kernel(const float* __restrict__ head_w, CircuitMasks cm) {
    int p = blockIdx.x * blockDim.x + threadIdx.x;
    if (p >= DIM) return;
    float acc = 0.f;
#pragma unroll
    for (int w = 0; w < NW; w++) {
        int par = __popc(p & cm.row2[w]) & 1;
        acc += par ? -head_w[w] : head_w[w];
    }
    g_weight[p] = acc;
}

__global__ __launch_bounds__(THREADS) void qsim_kernel(
    const float* __restrict__ state_batch,
    const float* __restrict__ params,
    const float* __restrict__ head_b,
    float* __restrict__ out,
    CircuitMasks cm) {
    __shared__ float2 s[DIM];
    __shared__ float2 f0[NW], f1[NW];     // per-wire product-state factors
    __shared__ float2 clo[64], chi[64];   // complex product tables
    __shared__ float2 gcs[NW];            // layer-1 RY (cos, sin)
    __shared__ float red[8];

    const int tid = threadIdx.x;
    const int b = blockIdx.x;

    // --- per-wire angles: RZ(phi) RY(theta + angle) |0>, layer-1 RY half angle
    if (tid < NW) {
        int w = tid;
        float ang = state_batch[(size_t)b * DIM + w];
        float th = 0.5f * (ang + params[w * 2 + 0]);     // params[0][w][0]
        float ph = 0.5f * params[w * 2 + 1];             // params[0][w][1]
        float sh, ch_, sp, cp;
        sincosf(th, &sh, &ch_);
        sincosf(ph, &sp, &cp);
        f0[w] = make_float2(cp * ch_, -sp * ch_);
        f1[w] = make_float2(cp * sh, sp * sh);
        float t2 = 0.5f * params[2 * NW + w * 2 + 0];    // params[1][w][0]
        float s2, c2;
        sincosf(t2, &s2, &c2);
        gcs[w] = make_float2(c2, s2);
        // (layer-1 RZ dropped: diagonal before a basis permutation + |.|^2)
    }
    __syncthreads();

    // --- product tables: bit j of index <-> wire (11-j)
    if (tid < 128) {
        int m = tid & 63;
        bool hi = tid >= 64;
        float2 acc = make_float2(1.f, 0.f);
#pragma unroll
        for (int j = 0; j < 6; j++) {
            int bit = (m >> j) & 1;
            int w = hi ? (5 - j) : (11 - j);
            float2 f = bit ? f1[w] : f0[w];
            acc = make_float2(acc.x * f.x - acc.y * f.y,
                              acc.x * f.y + acc.y * f.x);
        }
        if (hi) chi[m] = acc; else clo[m] = acc;
    }
    __syncthreads();

    // --- init statevector (product state, pre-first-CNOT-chain)
#pragma unroll
    for (int k = 0; k < DIM / THREADS; k++) {
        int p = tid + k * THREADS;
        float2 h = chi[p >> 6], l = clo[p & 63];
        s[p] = make_float2(h.x * l.x - h.y * l.y, h.x * l.y + h.y * l.x);
    }
    __syncthreads();

    // --- layer-1 RY gates in the CNOT-relabeled frame, 2 wires fused per pass
#pragma unroll
    for (int pass = 0; pass < 6; pass++) {
        const int Ma = cm.Ma[pass], Mb = cm.Mb[pass];
        const int Ra = cm.Ra[pass], Rb = cm.Rb[pass];
        const int q1 = cm.p1[pass], q2 = cm.p2[pass];
        const float ca = gcs[2 * pass].x, sa = gcs[2 * pass].y;
        const float cb = gcs[2 * pass + 1].x, sb = gcs[2 * pass + 1].y;
#pragma unroll
        for (int k = 0; k < (DIM / 4) / THREADS; k++) {
            int g = tid + k * THREADS;
            // coset representative: insert zero bits at q1 < q2
            int r = ((g >> q1) << (q1 + 1)) | (g & ((1 << q1) - 1));
            r = ((r >> q2) << (q2 + 1)) | (r & ((1 << q2) - 1));
            int pa = __popc(r & Ra) & 1;
            int pb = __popc(r & Rb) & 1;
            int q = r ^ (pa ? Ma : 0) ^ (pb ? Mb : 0);  // logical (0,0) slot
            int i00 = q, i10 = q ^ Ma, i01 = q ^ Mb, i11 = q ^ Ma ^ Mb;
            float2 v00 = s[i00], v10 = s[i10], v01 = s[i01], v11 = s[i11];
            // RY on wire A (pairs along Ma)
            float2 t00 = make_float2(ca * v00.x - sa * v10.x, ca * v00.y - sa * v10.y);
            float2 t10 = make_float2(sa * v00.x + ca * v10.x, sa * v00.y + ca * v10.y);
            float2 t01 = make_float2(ca * v01.x - sa * v11.x, ca * v01.y - sa * v11.y);
            float2 t11 = make_float2(sa * v01.x + ca * v11.x, sa * v01.y + ca * v11.y);
            // RY on wire B (pairs along Mb)
            s[i00] = make_float2(cb * t00.x - sb * t01.x, cb * t00.y - sb * t01.y);
            s[i01] = make_float2(sb * t00.x + cb * t01.x, sb * t00.y + cb * t01.y);
            s[i10] = make_float2(cb * t10.x - sb * t11.x, cb * t10.y - sb * t11.y);
            s[i11] = make_float2(sb * t10.x + cb * t11.x, sb * t10.y + cb * t11.y);
        }
        __syncthreads();
    }

    // --- measurement: sum |amp|^2 * weight(p); weight encodes M^2 relabel + head_w
    float acc = 0.f;
#pragma unroll
    for (int k = 0; k < DIM / THREADS; k++) {
        int p = tid + k * THREADS;
        float2 v = s[p];
        acc = fmaf(v.x * v.x + v.y * v.y, g_weight[p], acc);
    }
#pragma unroll
    for (int o = 16; o > 0; o >>= 1)
        acc += __shfl_xor_sync(0xffffffffu, acc, o);
    if ((tid & 31) == 0) red[tid >> 5] = acc;
    __syncthreads();
    if (tid == 0) {
        float t = 0.f;
#pragma unroll
        for (int i = 0; i < 8; i++) t += red[i];
        out[b] = t + head_b[0];
    }
}

// ---------------------------------------------------------------------------

extern "C" void kernel_launch(void* const* d_in, const int* in_sizes, int n_in,
                              void* d_out, int out_size) {
    const float* state_batch = (const float*)d_in[0];
    const float* params      = (const float*)d_in[1];
    const float* head_w      = (const float*)d_in[2];
    const float* head_b      = (const float*)d_in[3];
    float* out = (float*)d_out;

    CircuitMasks cm;
    compute_masks(&cm);

    weight_kernel<<<16, 256>>>(head_w, cm);
    qsim_kernel<<<out_size, THREADS>>>(state_batch, params, head_b, out, cm);
}

// round 2
// speedup vs baseline: 1.3713x; 1.3713x over previous
#include <cuda_runtime.h>
#include <stdint.h>

#define NW      12
#define DIM     4096
#define THREADS 256

// ---------------------------------------------------------------------------
// Host-side GF(2) machinery.
// CNOT chain acts as index relabel p -> M p. We store amplitudes in the
// q = M p basis, where every layer-1 gate is a standard bit-stride gate:
// wire w pairs along bit (11-w) of q, branch = that bit.
// Measurement sign masks become rows of M (since M^2 M^-1 = M).
// ---------------------------------------------------------------------------

struct CircuitMasks {
    int minv_col[12];   // bit-space columns of M^-1 (for init: p = Minv q)
    int mrow[12];       // bit-space rows of M (for measurement weights)
};

static inline int wire2bits(unsigned wiremask) {
    int m = 0;
    for (int v = 0; v < NW; v++)
        if ((wiremask >> v) & 1) m |= 1 << (11 - v);
    return m;
}

static void compute_masks(CircuitMasks* cm) {
    // rows of M (one CNOT chain), wire space
    unsigned M[NW];
    for (int w = 0; w < NW; w++) M[w] = 1u << w;
    for (int w = 0; w < NW - 1; w++) M[w + 1] ^= M[w];
    M[0] ^= M[NW - 1];

    // invert M via Gauss-Jordan (wire space)
    unsigned A[NW], Inv[NW];
    for (int i = 0; i < NW; i++) { A[i] = M[i]; Inv[i] = 1u << i; }
    for (int col = 0; col < NW; col++) {
        int piv = -1;
        for (int r = col; r < NW; r++)
            if ((A[r] >> col) & 1) { piv = r; break; }
        unsigned ta = A[col]; A[col] = A[piv]; A[piv] = ta;
        unsigned ti = Inv[col]; Inv[col] = Inv[piv]; Inv[piv] = ti;
        for (int r = 0; r < NW; r++)
            if (r != col && ((A[r] >> col) & 1)) { A[r] ^= A[col]; Inv[r] ^= Inv[col]; }
    }
    // wire-space column w of M^-1: bit v set iff Inv[v] has bit w
    unsigned colw[NW];
    for (int w = 0; w < NW; w++) {
        unsigned c = 0;
        for (int v = 0; v < NW; v++)
            if ((Inv[v] >> w) & 1) c |= 1u << v;
        colw[w] = c;
    }

    // bit-space column j of Minv corresponds to wire (11-j)
    for (int j = 0; j < NW; j++) cm->minv_col[j] = wire2bits(colw[11 - j]);
    for (int w = 0; w < NW; w++) cm->mrow[w] = wire2bits(M[w]);
}

// ---------------------------------------------------------------------------
// Device
// ---------------------------------------------------------------------------

__device__ float g_weight[DIM];

__global__ void weight_kernel(const float* __restrict__ head_w, CircuitMasks cm) {
    int q = blockIdx.x * blockDim.x + threadIdx.x;
    if (q >= DIM) return;
    float acc = 0.f;
#pragma unroll
    for (int w = 0; w < NW; w++) {
        int par = __popc(q & cm.mrow[w]) & 1;
        acc += par ? -head_w[w] : head_w[w];
    }
    g_weight[q] = acc;
}

// swizzled storage: phys(q) = q ^ ((q>>4)&15) -> conflict-free per 16-lane phase

__global__ __launch_bounds__(THREADS) void qsim_kernel(
    const float* __restrict__ state_batch,
    const float* __restrict__ params,
    const float* __restrict__ head_b,
    float* __restrict__ out,
    CircuitMasks cm) {
    __shared__ float2 s[DIM];
    __shared__ float2 f0[NW], f1[NW];     // per-wire product-state factors
    __shared__ float2 clo[64], chi[64];   // complex product tables (physical p space)
    __shared__ float2 gcs[NW];            // layer-1 RY (cos, sin) per wire
    __shared__ int    pr[16];             // Minv applied to low-4-bit nibbles
    __shared__ float  red[8];

    const int tid = threadIdx.x;
    const int b = blockIdx.x;

    // --- per-wire angles: RZ(phi) RY(theta + angle) |0>, layer-1 RY half angle
    if (tid < NW) {
        int w = tid;
        float ang = state_batch[(size_t)b * DIM + w];
        float th = 0.5f * (ang + params[w * 2 + 0]);     // params[0][w][0]
        float ph = 0.5f * params[w * 2 + 1];             // params[0][w][1]
        float sh, ch_, sp, cp;
        sincosf(th, &sh, &ch_);
        sincosf(ph, &sp, &cp);
        f0[w] = make_float2(cp * ch_, -sp * ch_);
        f1[w] = make_float2(cp * sh, sp * sh);
        float t2 = 0.5f * params[2 * NW + w * 2 + 0];    // params[1][w][0]
        float s2, c2;
        sincosf(t2, &s2, &c2);
        gcs[w] = make_float2(c2, s2);
        // (layer-1 RZ dropped: diagonal before a basis permutation + |.|^2)
    }
    if (tid < 16) {
        int r = tid, p = 0;
        if (r & 1) p ^= cm.minv_col[0];
        if (r & 2) p ^= cm.minv_col[1];
        if (r & 4) p ^= cm.minv_col[2];
        if (r & 8) p ^= cm.minv_col[3];
        pr[r] = p;
    }
    __syncthreads();

    // --- product tables in physical space: bit j of p <-> wire (11-j)
    if (tid < 128) {
        int m = tid & 63;
        bool hi = tid >= 64;
        float2 acc = make_float2(1.f, 0.f);
#pragma unroll
        for (int j = 0; j < 6; j++) {
            int bit = (m >> j) & 1;
            int w = hi ? (5 - j) : (11 - j);
            float2 f = bit ? f1[w] : f0[w];
            acc = make_float2(acc.x * f.x - acc.y * f.y,
                              acc.x * f.y + acc.y * f.x);
        }
        if (hi) chi[m] = acc; else clo[m] = acc;
    }
    __syncthreads();

    // --- init 16 amplitudes straight into registers (mapping1: q = (tid<<4)|r)
    int pb = 0;
#pragma unroll
    for (int i = 0; i < 8; i++)
        if ((tid >> i) & 1) pb ^= cm.minv_col[i + 4];

    float2 v[16];
#pragma unroll
    for (int r = 0; r < 16; r++) {
        int p = pb ^ pr[r];
        float2 lo = clo[p & 63], hi = chi[p >> 6];
        v[r] = make_float2(hi.x * lo.x - hi.y * lo.y,
                           hi.x * lo.y + hi.y * lo.x);
    }

    // gate on register bit bp with angle of 'wire'
#define APPLY_BIT(bp, wire) {                                           \
        float c = gcs[wire].x, sn = gcs[wire].y;                        \
        _Pragma("unroll")                                               \
        for (int r = 0; r < 16; r++) if (!(r & (1 << bp))) {            \
            int r1 = r | (1 << bp);                                     \
            float2 a = v[r], d = v[r1];                                 \
            v[r]  = make_float2(c * a.x - sn * d.x, c * a.y - sn * d.y);\
            v[r1] = make_float2(sn * a.x + c * d.x, sn * a.y + c * d.y);\
        }                                                               \
    }

    // --- phase 1: q bits 0..3 in regs -> wires 11,10,9,8
    APPLY_BIT(0, 11); APPLY_BIT(1, 10); APPLY_BIT(2, 9); APPLY_BIT(3, 8);

    const int tx = tid & 15;

    // transpose 1: write mapping1 (phys = (t<<4) | (r^tx))
#pragma unroll
    for (int r = 0; r < 16; r++)
        s[(tid << 4) | (r ^ tx)] = v[r];
    __syncthreads();

    // --- phase 2: read mapping2 (regs = q bits 4..7)
    const int base2 = ((tid >> 4) << 8);
#pragma unroll
    for (int r = 0; r < 16; r++)
        v[r] = s[base2 | (r << 4) | (tx ^ r)];

    // wires 7,6,5,4
    APPLY_BIT(0, 7); APPLY_BIT(1, 6); APPLY_BIT(2, 5); APPLY_BIT(3, 4);

    // write back to the SAME slots this thread read -> no sync needed before
#pragma unroll
    for (int r = 0; r < 16; r++)
        s[base2 | (r << 4) | (tx ^ r)] = v[r];
    __syncthreads();

    // --- phase 3: read mapping3 (regs = q bits 8..11)
    const int thi = tid & 0xF0;
    const int swz3 = tx ^ (tid >> 4);
#pragma unroll
    for (int r = 0; r < 16; r++)
        v[r] = s[(r << 8) | thi | swz3];

    // wires 3,2,1,0
    APPLY_BIT(0, 3); APPLY_BIT(1, 2); APPLY_BIT(2, 1); APPLY_BIT(3, 0);

    // --- measurement: weight table indexed in q space (rows of M folded in)
    float acc = 0.f;
#pragma unroll
    for (int r = 0; r < 16; r++) {
        float2 a = v[r];
        acc = fmaf(a.x * a.x + a.y * a.y, g_weight[(r << 8) | tid], acc);
    }
#pragma unroll
    for (int o = 16; o > 0; o >>= 1)
        acc += __shfl_xor_sync(0xffffffffu, acc, o);
    if ((tid & 31) == 0) red[tid >> 5] = acc;
    __syncthreads();
    if (tid == 0) {
        float t = 0.f;
#pragma unroll
        for (int i = 0; i < 8; i++) t += red[i];
        out[b] = t + head_b[0];
    }
#undef APPLY_BIT
}

// ---------------------------------------------------------------------------

extern "C" void kernel_launch(void* const* d_in, const int* in_sizes, int n_in,
                              void* d_out, int out_size) {
    const float* state_batch = (const float*)d_in[0];
    const float* params      = (const float*)d_in[1];
    const float* head_w      = (const float*)d_in[2];
    const float* head_b      = (const float*)d_in[3];
    float* out = (float*)d_out;

    CircuitMasks cm;
    compute_masks(&cm);

    weight_kernel<<<16, 256>>>(head_w, cm);
    qsim_kernel<<<out_size, THREADS>>>(state_batch, params, head_b, out, cm);
}

// round 3
// speedup vs baseline: 1.4410x; 1.0508x over previous
#include <cuda_runtime.h>
#include <stdint.h>

#define NW      12
#define DIM     4096
#define THREADS 256

typedef unsigned long long u64;

// ---------------------------------------------------------------------------
// Host-side GF(2) machinery.
// CNOT chain acts as index relabel p -> M p. We store amplitudes in the
// q = M p basis, where every layer-1 gate is a standard bit-stride gate:
// wire w pairs along bit (11-w) of q, branch = that bit.
// Measurement sign masks become rows of M (since M^2 M^-1 = M).
// ---------------------------------------------------------------------------

struct CircuitMasks {
    int minv_col[12];   // bit-space columns of M^-1 (for init: p = Minv q)
    int mrow[12];       // bit-space rows of M (for measurement weights)
};

static inline int wire2bits(unsigned wiremask) {
    int m = 0;
    for (int v = 0; v < NW; v++)
        if ((wiremask >> v) & 1) m |= 1 << (11 - v);
    return m;
}

static void compute_masks(CircuitMasks* cm) {
    unsigned M[NW];
    for (int w = 0; w < NW; w++) M[w] = 1u << w;
    for (int w = 0; w < NW - 1; w++) M[w + 1] ^= M[w];
    M[0] ^= M[NW - 1];

    unsigned A[NW], Inv[NW];
    for (int i = 0; i < NW; i++) { A[i] = M[i]; Inv[i] = 1u << i; }
    for (int col = 0; col < NW; col++) {
        int piv = -1;
        for (int r = col; r < NW; r++)
            if ((A[r] >> col) & 1) { piv = r; break; }
        unsigned ta = A[col]; A[col] = A[piv]; A[piv] = ta;
        unsigned ti = Inv[col]; Inv[col] = Inv[piv]; Inv[piv] = ti;
        for (int r = 0; r < NW; r++)
            if (r != col && ((A[r] >> col) & 1)) { A[r] ^= A[col]; Inv[r] ^= Inv[col]; }
    }
    unsigned colw[NW];
    for (int w = 0; w < NW; w++) {
        unsigned c = 0;
        for (int v = 0; v < NW; v++)
            if ((Inv[v] >> w) & 1) c |= 1u << v;
        colw[w] = c;
    }

    for (int j = 0; j < NW; j++) cm->minv_col[j] = wire2bits(colw[11 - j]);
    for (int w = 0; w < NW; w++) cm->mrow[w] = wire2bits(M[w]);
}

// ---------------------------------------------------------------------------
// Device
// ---------------------------------------------------------------------------

__device__ float g_weight[DIM];

__global__ void weight_kernel(const float* __restrict__ head_w, CircuitMasks cm) {
    int q = blockIdx.x * blockDim.x + threadIdx.x;
    if (q >= DIM) return;
    float acc = 0.f;
#pragma unroll
    for (int w = 0; w < NW; w++) {
        int par = __popc(q & cm.mrow[w]) & 1;
        acc += par ? -head_w[w] : head_w[w];
    }
    g_weight[q] = acc;
}

// packed f32x2 helpers (Blackwell FFMA2 path — ptxas never auto-fuses this)
__device__ __forceinline__ u64 pack2(float a, float b) {
    u64 r; asm("mov.b64 %0, {%1, %2};" : "=l"(r) : "f"(a), "f"(b)); return r;
}
__device__ __forceinline__ u64 ffma2(u64 a, u64 b, u64 c) {
    u64 d; asm("fma.rn.f32x2 %0, %1, %2, %3;" : "=l"(d) : "l"(a), "l"(b), "l"(c)); return d;
}
__device__ __forceinline__ u64 fmul2(u64 a, u64 b) {
    u64 d; asm("mul.rn.f32x2 %0, %1, %2;" : "=l"(d) : "l"(a), "l"(b)); return d;
}
__device__ __forceinline__ float2 u2f(u64 a) {
    float2 f; asm("mov.b64 {%0, %1}, %2;" : "=f"(f.x), "=f"(f.y) : "l"(a)); return f;
}

// swizzled storage: phys(q) = q ^ ((q>>4)&15) -> conflict-free per 16-lane phase

__global__ __launch_bounds__(THREADS) void qsim_kernel(
    const float* __restrict__ state_batch,
    const float* __restrict__ params,
    const float* __restrict__ head_b,
    float* __restrict__ out,
    CircuitMasks cm) {
    __shared__ u64    s[DIM];
    __shared__ float2 f0[NW], f1[NW];     // per-wire product-state factors
    __shared__ float2 clo[64], chi[64];   // complex product tables (physical p space)
    __shared__ float2 gcs[NW];            // layer-1 RY (cos, sin) per wire
    __shared__ int    pr[16];             // Minv applied to low-4-bit nibbles
    __shared__ float  red[8];

    const int tid = threadIdx.x;
    const int b = blockIdx.x;

    // --- per-wire angles: RZ(phi) RY(theta + angle) |0>, layer-1 RY half angle
    if (tid < NW) {
        int w = tid;
        float ang = state_batch[(size_t)b * DIM + w];
        float th = 0.5f * (ang + params[w * 2 + 0]);     // params[0][w][0]
        float ph = 0.5f * params[w * 2 + 1];             // params[0][w][1]
        float sh, ch_, sp, cp;
        sincosf(th, &sh, &ch_);
        sincosf(ph, &sp, &cp);
        f0[w] = make_float2(cp * ch_, -sp * ch_);
        f1[w] = make_float2(cp * sh, sp * sh);
        float t2 = 0.5f * params[2 * NW + w * 2 + 0];    // params[1][w][0]
        float s2, c2;
        sincosf(t2, &s2, &c2);
        gcs[w] = make_float2(c2, s2);
        // (layer-1 RZ dropped: diagonal before a basis permutation + |.|^2)
    }
    if (tid < 16) {
        int r = tid, p = 0;
        if (r & 1) p ^= cm.minv_col[0];
        if (r & 2) p ^= cm.minv_col[1];
        if (r & 4) p ^= cm.minv_col[2];
        if (r & 8) p ^= cm.minv_col[3];
        pr[r] = p;
    }
    __syncthreads();

    // --- product tables in physical space: bit j of p <-> wire (11-j)
    if (tid < 128) {
        int m = tid & 63;
        bool hi = tid >= 64;
        float2 acc = make_float2(1.f, 0.f);
#pragma unroll
        for (int j = 0; j < 6; j++) {
            int bit = (m >> j) & 1;
            int w = hi ? (5 - j) : (11 - j);
            float2 f = bit ? f1[w] : f0[w];
            acc = make_float2(acc.x * f.x - acc.y * f.y,
                              acc.x * f.y + acc.y * f.x);
        }
        if (hi) chi[m] = acc; else clo[m] = acc;
    }
    __syncthreads();

    // --- init 16 amplitudes straight into registers (mapping1: q = (tid<<4)|r)
    int pb = 0;
#pragma unroll
    for (int i = 0; i < 8; i++)
        if ((tid >> i) & 1) pb ^= cm.minv_col[i + 4];

    u64 v[16];
#pragma unroll
    for (int r = 0; r < 16; r++) {
        int p = pb ^ pr[r];
        float2 lo = clo[p & 63], hi = chi[p >> 6];
        v[r] = pack2(fmaf(hi.x, lo.x, -hi.y * lo.y),
                     fmaf(hi.x, lo.y,  hi.y * lo.x));
    }

    // gate on register bit bp with angle of 'wire' (packed f32x2 math)
#define APPLY_BIT(bp, wire) {                                           \
        float c_ = gcs[wire].x, sn_ = gcs[wire].y;                      \
        u64 c2_ = pack2(c_, c_), s2_ = pack2(sn_, sn_);                 \
        u64 ns2_ = pack2(-sn_, -sn_);                                   \
        _Pragma("unroll")                                               \
        for (int r = 0; r < 16; r++) if (!(r & (1 << bp))) {            \
            int r1 = r | (1 << bp);                                     \
            u64 a_ = v[r], d_ = v[r1];                                  \
            v[r]  = ffma2(c2_, a_, fmul2(ns2_, d_));                    \
            v[r1] = ffma2(s2_, a_, fmul2(c2_,  d_));                    \
        }                                                               \
    }

    // --- phase 1: q bits 0..3 in regs -> wires 11,10,9,8
    APPLY_BIT(0, 11); APPLY_BIT(1, 10); APPLY_BIT(2, 9); APPLY_BIT(3, 8);

    const int tx = tid & 15;

    // transpose 1: write mapping1 (phys = (t<<4) | (r^tx))
#pragma unroll
    for (int r = 0; r < 16; r++)
        s[(tid << 4) | (r ^ tx)] = v[r];
    __syncthreads();

    // --- phase 2: read mapping2 (regs = q bits 4..7)
    const int base2 = ((tid >> 4) << 8);
#pragma unroll
    for (int r = 0; r < 16; r++)
        v[r] = s[base2 | (r << 4) | (tx ^ r)];

    // wires 7,6,5,4
    APPLY_BIT(0, 7); APPLY_BIT(1, 6); APPLY_BIT(2, 5); APPLY_BIT(3, 4);

    // write back to the SAME slots this thread read -> no sync needed before
#pragma unroll
    for (int r = 0; r < 16; r++)
        s[base2 | (r << 4) | (tx ^ r)] = v[r];
    __syncthreads();

    // --- phase 3: read mapping3 (regs = q bits 8..11)
    const int thi = tid & 0xF0;
    const int swz3 = tx ^ (tid >> 4);
#pragma unroll
    for (int r = 0; r < 16; r++)
        v[r] = s[(r << 8) | thi | swz3];

    // wires 3,2,1,0
    APPLY_BIT(0, 3); APPLY_BIT(1, 2); APPLY_BIT(2, 1); APPLY_BIT(3, 0);

    // --- measurement: weight table indexed in q space (rows of M folded in)
    float acc = 0.f;
#pragma unroll
    for (int r = 0; r < 16; r++) {
        float2 a = u2f(v[r]);
        acc = fmaf(fmaf(a.x, a.x, a.y * a.y), g_weight[(r << 8) | tid], acc);
    }
#pragma unroll
    for (int o = 16; o > 0; o >>= 1)
        acc += __shfl_xor_sync(0xffffffffu, acc, o);
    if ((tid & 31) == 0) red[tid >> 5] = acc;
    __syncthreads();
    if (tid == 0) {
        float t = 0.f;
#pragma unroll
        for (int i = 0; i < 8; i++) t += red[i];
        out[b] = t + head_b[0];
    }
#undef APPLY_BIT
}

// ---------------------------------------------------------------------------

extern "C" void kernel_launch(void* const* d_in, const int* in_sizes, int n_in,
                              void* d_out, int out_size) {
    const float* state_batch = (const float*)d_in[0];
    const float* params      = (const float*)d_in[1];
    const float* head_w      = (const float*)d_in[2];
    const float* head_b      = (const float*)d_in[3];
    float* out = (float*)d_out;

    CircuitMasks cm;
    compute_masks(&cm);

    weight_kernel<<<16, 256>>>(head_w, cm);
    qsim_kernel<<<out_size, THREADS>>>(state_batch, params, head_b, out, cm);
}